// round 11
// baseline (speedup 1.0000x reference)
#include <cuda_runtime.h>
#include <cuda_bf16.h>
#include <cstdint>

#define NA 100000
#define NB 100000
#define D 64
#define NTOT (NA + NA + NB)                 // deg/off layout: [aa->A | ba->A | ab->B]
#define ECAP 2000000
#define AS 72                               // smem row stride (bf16), conflict-free
#define CGRID 4096                          // 64x64 degree-pair grid (A); 1-D for B
#define TROWSA (CGRID + NA)
#define TROWSB (CGRID + NB)
#define SCAN_NBLK ((NTOT + 1023) / 1024)    // 293

// ======================= scratch (zero-initialized at module load) ===========
__device__ int      g_deg[NTOT];            // zeroed at end of every run
__device__ unsigned g_state[SCAN_NBLK];     // scan lookback state; zeroed at end
__device__ int      g_novf[2];              // overflow counters; zeroed at end
__device__ int      g_off[NTOT + 1];
__device__ int      g_cur[NTOT];
__device__ int      g_csr[ECAP];            // combo-id of src, grouped by dst
__device__ int      g_cidA[NA];
__device__ int      g_cidB[NB];
__device__ int2     g_ovfA[NA];
__device__ int      g_ovfB[NB];
__device__ float    g_TzA[TROWSA * D];
__device__ float    g_Taa[TROWSA * D];
__device__ float    g_Tab[TROWSA * D];
__device__ float    g_TzB[TROWSB * D];
__device__ float    g_Tba[TROWSB * D];

// ======================= sparse machinery ====================================
__global__ void k_deg_all(const int* __restrict__ d_aa, int Eaa,
                          const int* __restrict__ d_ba, int Eba,
                          const int* __restrict__ d_ab, int Eab) {
    int i = blockIdx.x * blockDim.x + threadIdx.x;
    if (i < Eaa) {
        atomicAdd(&g_deg[d_aa[i]], 1);
    } else if (i < Eaa + Eba) {
        atomicAdd(&g_deg[NA + d_ba[i - Eaa]], 1);
    } else if (i < Eaa + Eba + Eab) {
        atomicAdd(&g_deg[2 * NA + d_ab[i - Eaa - Eba]], 1);
    }
}

// single-pass decoupled-lookback exclusive scan (warp-parallel lookback)
// + combo-id assignment. All SCAN_NBLK blocks simultaneously resident.
__global__ void __launch_bounds__(1024) k_scan_cid() {
    __shared__ int wsum[32];
    __shared__ int s_total, s_prefix;
    int b = blockIdx.x, t = threadIdx.x;
    int i = b * 1024 + t;
    int v = (i < NTOT) ? g_deg[i] : 0;
    int x = v;
#pragma unroll
    for (int o = 1; o < 32; o <<= 1) {
        int y = __shfl_up_sync(0xffffffffu, x, o);
        if ((t & 31) >= o) x += y;
    }
    if ((t & 31) == 31) wsum[t >> 5] = x;
    __syncthreads();
    if (t < 32) {
        int w = wsum[t];
        int xx = w;
#pragma unroll
        for (int o = 1; o < 32; o <<= 1) {
            int y = __shfl_up_sync(0xffffffffu, xx, o);
            if (t >= o) xx += y;
        }
        wsum[t] = xx - w;
        if (t == 31) {
            s_total = xx;
            unsigned st = ((b == 0 ? 2u : 1u) << 30) | (unsigned)xx;
            atomicExch(&g_state[b], st);
        }
    }
    __syncthreads();
    int excl = x - v + wsum[t >> 5];

    if (t < 32) {
        int pref = 0;
        if (b > 0) {
            int j = b - 1;
            while (true) {
                int idx = j - t;
                unsigned st;
                do {
                    st = (idx >= 0) ? atomicAdd(&g_state[idx], 0u) : (2u << 30);
                } while (__any_sync(0xffffffffu, (st >> 30) == 0));
                unsigned incmask = __ballot_sync(0xffffffffu, (st >> 30) >= 2);
                int firstInc = __ffs(incmask) - 1;
                int val = (int)(st & 0x3FFFFFFFu);
                int take = (firstInc >= 0) ? ((t <= firstInc) ? val : 0) : val;
#pragma unroll
                for (int o = 16; o; o >>= 1) take += __shfl_down_sync(0xffffffffu, take, o);
                take = __shfl_sync(0xffffffffu, take, 0);
                pref += take;
                if (firstInc >= 0) break;
                j -= 32;
            }
            if (t == 0) atomicExch(&g_state[b], (2u << 30) | (unsigned)(pref + s_total));
        }
        if (t == 0) s_prefix = pref;
    }
    __syncthreads();
    int off = s_prefix + excl;
    if (i < NTOT) { g_off[i] = off; g_cur[i] = off; }
    if (i == NTOT - 1) g_off[NTOT] = off + v;

    if (i < NA) {
        int d1 = v, d2 = g_deg[NA + i];
        int cid;
        if (d1 < 64 && d2 < 64) cid = d1 * 64 + d2;
        else { int o = atomicAdd(&g_novf[0], 1); g_ovfA[o] = make_int2(d1, d2); cid = CGRID + o; }
        g_cidA[i] = cid;
    } else if (i < NA + NB) {
        int d = g_deg[NA + i];
        int cid;
        if (d < CGRID) cid = d;
        else { int o = atomicAdd(&g_novf[1], 1); g_ovfB[o] = d; cid = CGRID + o; }
        g_cidB[i - NA] = cid;
    }
}

// counting-sort fill; stores the SRC COMBO-ID
__global__ void k_fill_all(const int* __restrict__ s_aa, const int* __restrict__ d_aa, int Eaa,
                           const int* __restrict__ s_ba, const int* __restrict__ d_ba, int Eba,
                           const int* __restrict__ s_ab, const int* __restrict__ d_ab, int Eab) {
    int i = blockIdx.x * blockDim.x + threadIdx.x;
    int cid, base, dstv;
    if (i < Eaa) { cid = __ldg(&g_cidA[s_aa[i]]); dstv = d_aa[i]; base = 0; }
    else if (i < Eaa + Eba) { int j = i - Eaa; cid = __ldg(&g_cidB[s_ba[j]]); dstv = d_ba[j]; base = NA; }
    else if (i < Eaa + Eba + Eab) { int j = i - Eaa - Eba; cid = __ldg(&g_cidA[s_ab[j]]); dstv = d_ab[j]; base = 2 * NA; }
    else return;
    int pos = atomicAdd(&g_cur[base + dstv], 1);
    g_csr[pos] = cid;
}

// zero scratch (runs on side stream concurrent with GATHER)
__global__ void k_zero_end() {
    int i = blockIdx.x * blockDim.x + threadIdx.x;
    if (i < NTOT / 4) reinterpret_cast<int4*>(g_deg)[i] = make_int4(0, 0, 0, 0);
    if (i < SCAN_NBLK) g_state[i] = 0;
    if (i == 0) { g_novf[0] = 0; g_novf[1] = 0; }
}

// ======================= MMA helpers =========================================
__device__ __forceinline__ void mma_bf16(float c[4], const uint32_t a[4],
                                         uint32_t b0, uint32_t b1) {
    asm volatile("mma.sync.aligned.m16n8k16.row.col.f32.bf16.bf16.f32 "
                 "{%0,%1,%2,%3}, {%4,%5,%6,%7}, {%8,%9}, {%0,%1,%2,%3};"
                 : "+f"(c[0]), "+f"(c[1]), "+f"(c[2]), "+f"(c[3])
                 : "r"(a[0]), "r"(a[1]), "r"(a[2]), "r"(a[3]), "r"(b0), "r"(b1));
}
__device__ __forceinline__ void pack_hl(float x, float y, uint32_t& hi, uint32_t& lo) {
    __nv_bfloat162 H, L;
    H.x = __float2bfloat16(x); H.y = __float2bfloat16(y);
    L.x = __float2bfloat16(x - __bfloat162float(H.x));
    L.y = __float2bfloat16(y - __bfloat162float(H.y));
    hi = *reinterpret_cast<uint32_t*>(&H);
    lo = *reinterpret_cast<uint32_t*>(&L);
}
__device__ __forceinline__ void gemm_tile(float acc[8][4],
                                          const uint32_t* Ahi, const uint32_t* Alo,
                                          const __nv_bfloat16* whi, int g, int t) {
    const __nv_bfloat16* wlo = whi + 64 * AS;
#pragma unroll
    for (int nt = 0; nt < 8; nt++) {
        const __nv_bfloat16* bh = whi + (nt * 8 + g) * AS + 2 * t;
        const __nv_bfloat16* bl = wlo + (nt * 8 + g) * AS + 2 * t;
#pragma unroll
        for (int kc = 0; kc < 4; kc++) {
            uint32_t bh0 = *reinterpret_cast<const uint32_t*>(bh + kc * 16);
            uint32_t bh1 = *reinterpret_cast<const uint32_t*>(bh + kc * 16 + 8);
            uint32_t bl0 = *reinterpret_cast<const uint32_t*>(bl + kc * 16);
            uint32_t bl1 = *reinterpret_cast<const uint32_t*>(bl + kc * 16 + 8);
            mma_bf16(acc[nt], &Ahi[kc * 4], bh0, bh1);
            mma_bf16(acc[nt], &Ahi[kc * 4], bl0, bl1);
            mma_bf16(acc[nt], &Alo[kc * 4], bh0, bh1);
        }
    }
}
__device__ __forceinline__ void c2a(float acc[8][4], const float* __restrict__ bias,
                                    uint32_t A2hi[16], uint32_t A2lo[16], int t) {
#pragma unroll
    for (int kc = 0; kc < 4; kc++) {
        int nt0 = 2 * kc, nt1 = nt0 + 1;
        float b00 = __ldg(bias + nt0 * 8 + 2 * t), b01 = __ldg(bias + nt0 * 8 + 2 * t + 1);
        float b10 = __ldg(bias + nt1 * 8 + 2 * t), b11 = __ldg(bias + nt1 * 8 + 2 * t + 1);
        float x0 = fmaxf(acc[nt0][0] + b00, 0.f), x1 = fmaxf(acc[nt0][1] + b01, 0.f);
        float x2 = fmaxf(acc[nt0][2] + b00, 0.f), x3 = fmaxf(acc[nt0][3] + b01, 0.f);
        float y0 = fmaxf(acc[nt1][0] + b10, 0.f), y1 = fmaxf(acc[nt1][1] + b11, 0.f);
        float y2 = fmaxf(acc[nt1][2] + b10, 0.f), y3 = fmaxf(acc[nt1][3] + b11, 0.f);
        pack_hl(x0, x1, A2hi[kc * 4 + 0], A2lo[kc * 4 + 0]);
        pack_hl(x2, x3, A2hi[kc * 4 + 1], A2lo[kc * 4 + 1]);
        pack_hl(y0, y1, A2hi[kc * 4 + 2], A2lo[kc * 4 + 2]);
        pack_hl(y2, y3, A2hi[kc * 4 + 3], A2lo[kc * 4 + 3]);
    }
}
__device__ __forceinline__ void store_tile(float acc[8][4], const float* __restrict__ bias,
                                           float* __restrict__ out, int row0, int row1,
                                           int R, int t) {
#pragma unroll
    for (int nt = 0; nt < 8; nt++) {
        int col = nt * 8 + 2 * t;
        float bx = bias ? __ldg(bias + col) : 0.f;
        float by = bias ? __ldg(bias + col + 1) : 0.f;
        float2 v0 = make_float2(acc[nt][0] + bx, acc[nt][1] + by);
        float2 v1 = make_float2(acc[nt][2] + bx, acc[nt][3] + by);
        if (row0 < R) *reinterpret_cast<float2*>(out + (size_t)row0 * 64 + col) = v0;
        if (row1 < R) *reinterpret_cast<float2*>(out + (size_t)row1 * 64 + col) = v1;
    }
}
__device__ __forceinline__ void stage_w(__nv_bfloat16* sm, const float* const* wsrc,
                                        int nm, int tid) {
    for (int m = 0; m < nm; m++) {
        const float* w = wsrc[m];
        __nv_bfloat16* whi = sm + m * 2 * 64 * AS;
        __nv_bfloat16* wlo = whi + 64 * AS;
        for (int i = tid; i < 4096; i += 256) {
            int k = i >> 6, n = i & 63;
            float x = w[i];
            __nv_bfloat16 hi = __float2bfloat16(x);
            whi[n * AS + k] = hi;
            wlo[n * AS + k] = __float2bfloat16(x - __bfloat162float(hi));
        }
    }
}

// ======================= combo-table GEMM kernels =============================
#define SMEM_A_BYTES (5 * 2 * 64 * AS * 2)   // 92160
__global__ void __launch_bounds__(256) k_gemmA(
        const float* __restrict__ embA, const float* __restrict__ embB,
        const float* __restrict__ Waa0, const float* __restrict__ baa0,
        const float* __restrict__ Wba0, const float* __restrict__ bba0,
        const float* __restrict__ WnA0, const float* __restrict__ bnA0,
        const float* __restrict__ Waa1, const float* __restrict__ baa1,
        const float* __restrict__ Wab1, const float* __restrict__ bab1,
        const float* __restrict__ WnA1, const float* __restrict__ bnA1,
        const float* __restrict__ WnB1blk1, int is_ovf) {
    int row_off = is_ovf ? CGRID : 0;
    int nrows   = is_ovf ? g_novf[0] : CGRID;
    if ((int)blockIdx.x * 128 >= nrows) return;
    int limit = row_off + nrows;

    extern __shared__ __nv_bfloat16 sm[];
    __shared__ float sA[64], sB[64], v1[64], v2[64], sv[192];
    int tid = threadIdx.x;
    const float* wsrc[5] = { Waa1, Wab1, WnA1, WnA1 + 4096, WnB1blk1 };
    stage_w(sm, wsrc, 5, tid);
    if (tid < 64) { sA[tid] = embA[tid]; sB[tid] = embB[tid]; }
    __syncthreads();
    if (tid < 64) {
        int c = tid;
        float a0 = baa0[c], a2 = bba0[c];
        for (int k = 0; k < 64; k++) {
            a0 += sA[k] * Waa0[k * 64 + c];
            a2 += sB[k] * Wba0[k * 64 + c];
        }
        v1[c] = fmaxf(a0, 0.f); v2[c] = fmaxf(a2, 0.f);
    }
    __syncthreads();
    if (tid < 64) {
        int c = tid;
        float cA = bnA0[c], uaa = 0.f, uba = 0.f;
        for (int k = 0; k < 64; k++) {
            cA  += sA[k] * WnA0[k * 64 + c];
            uaa += v1[k] * WnA0[(64 + k) * 64 + c];
            uba += v2[k] * WnA0[(128 + k) * 64 + c];
        }
        sv[c] = cA; sv[64 + c] = uaa; sv[128 + c] = uba;
    }
    __syncthreads();

    int lane = tid & 31, wid = tid >> 5;
    int g = lane >> 2, t = lane & 3;
    int row0 = row_off + blockIdx.x * 128 + wid * 16 + g, row1 = row0 + 8;
    int r0 = min(row0, limit - 1), r1 = min(row1, limit - 1);
    float d10, d20, d11, d21;
    if (r0 < CGRID) { d10 = (float)(r0 >> 6); d20 = (float)(r0 & 63); }
    else { int2 dd = g_ovfA[r0 - CGRID]; d10 = (float)dd.x; d20 = (float)dd.y; }
    if (r1 < CGRID) { d11 = (float)(r1 >> 6); d21 = (float)(r1 & 63); }
    else { int2 dd = g_ovfA[r1 - CGRID]; d11 = (float)dd.x; d21 = (float)dd.y; }

    uint32_t Ahi[16], Alo[16];
#pragma unroll
    for (int kc = 0; kc < 4; kc++) {
        int c0 = kc * 16 + 2 * t;
#pragma unroll
        for (int half = 0; half < 2; half++) {
            int c = c0 + half * 8;
            float p0 = sv[c],     u0 = sv[64 + c],     w0 = sv[128 + c];
            float p1 = sv[c + 1], u1 = sv[64 + c + 1], w1 = sv[128 + c + 1];
            float h00 = fmaxf(p0 + d10 * u0 + d20 * w0, 0.f);
            float h01 = fmaxf(p1 + d10 * u1 + d20 * w1, 0.f);
            float h10 = fmaxf(p0 + d11 * u0 + d21 * w0, 0.f);
            float h11 = fmaxf(p1 + d11 * u1 + d21 * w1, 0.f);
            pack_hl(h00, h01, Ahi[kc * 4 + half * 2 + 0], Alo[kc * 4 + half * 2 + 0]);
            pack_hl(h10, h11, Ahi[kc * 4 + half * 2 + 1], Alo[kc * 4 + half * 2 + 1]);
        }
    }

    float acc[8][4], acc2[8][4];
    uint32_t A2hi[16], A2lo[16];

#pragma unroll
    for (int nt = 0; nt < 8; nt++) { acc[nt][0]=0.f; acc[nt][1]=0.f; acc[nt][2]=0.f; acc[nt][3]=0.f; }
    gemm_tile(acc, Ahi, Alo, sm + 2 * 2 * 64 * AS, g, t);
    store_tile(acc, bnA1, g_TzA, row0, row1, limit, t);

#pragma unroll
    for (int nt = 0; nt < 8; nt++) { acc[nt][0]=0.f; acc[nt][1]=0.f; acc[nt][2]=0.f; acc[nt][3]=0.f; }
    gemm_tile(acc, Ahi, Alo, sm, g, t);
    c2a(acc, baa1, A2hi, A2lo, t);
#pragma unroll
    for (int nt = 0; nt < 8; nt++) { acc2[nt][0]=0.f; acc2[nt][1]=0.f; acc2[nt][2]=0.f; acc2[nt][3]=0.f; }
    gemm_tile(acc2, A2hi, A2lo, sm + 3 * 2 * 64 * AS, g, t);
    store_tile(acc2, nullptr, g_Taa, row0, row1, limit, t);

#pragma unroll
    for (int nt = 0; nt < 8; nt++) { acc[nt][0]=0.f; acc[nt][1]=0.f; acc[nt][2]=0.f; acc[nt][3]=0.f; }
    gemm_tile(acc, Ahi, Alo, sm + 1 * 2 * 64 * AS, g, t);
    c2a(acc, bab1, A2hi, A2lo, t);
#pragma unroll
    for (int nt = 0; nt < 8; nt++) { acc2[nt][0]=0.f; acc2[nt][1]=0.f; acc2[nt][2]=0.f; acc2[nt][3]=0.f; }
    gemm_tile(acc2, A2hi, A2lo, sm + 4 * 2 * 64 * AS, g, t);
    store_tile(acc2, nullptr, g_Tab, row0, row1, limit, t);
}

#define SMEM_B_BYTES (3 * 2 * 64 * AS * 2)   // 55296
__global__ void __launch_bounds__(256) k_gemmB(
        const float* __restrict__ embA, const float* __restrict__ embB,
        const float* __restrict__ Wab0, const float* __restrict__ bab0,
        const float* __restrict__ WnB0, const float* __restrict__ bnB0,
        const float* __restrict__ Wba1, const float* __restrict__ bba1,
        const float* __restrict__ WnB1, const float* __restrict__ bnB1,
        const float* __restrict__ WnA1blk2, int is_ovf) {
    int row_off = is_ovf ? CGRID : 0;
    int nrows   = is_ovf ? g_novf[1] : CGRID;
    if ((int)blockIdx.x * 128 >= nrows) return;
    int limit = row_off + nrows;

    extern __shared__ __nv_bfloat16 sm[];
    __shared__ float sA[64], sB[64], v1[64], sv[128];
    int tid = threadIdx.x;
    const float* wsrc[3] = { Wba1, WnB1, WnA1blk2 };
    stage_w(sm, wsrc, 3, tid);
    if (tid < 64) { sA[tid] = embA[tid]; sB[tid] = embB[tid]; }
    __syncthreads();
    if (tid < 64) {
        int c = tid;
        float a1 = bab0[c];
        for (int k = 0; k < 64; k++) a1 += sA[k] * Wab0[k * 64 + c];
        v1[c] = fmaxf(a1, 0.f);
    }
    __syncthreads();
    if (tid < 64) {
        int c = tid;
        float cB = bnB0[c], uab = 0.f;
        for (int k = 0; k < 64; k++) {
            cB  += sB[k] * WnB0[k * 64 + c];
            uab += v1[k] * WnB0[(64 + k) * 64 + c];
        }
        sv[c] = cB; sv[64 + c] = uab;
    }
    __syncthreads();

    int lane = tid & 31, wid = tid >> 5;
    int g = lane >> 2, t = lane & 3;
    int row0 = row_off + blockIdx.x * 128 + wid * 16 + g, row1 = row0 + 8;
    int r0 = min(row0, limit - 1), r1 = min(row1, limit - 1);
    float d0 = (r0 < CGRID) ? (float)r0 : (float)g_ovfB[r0 - CGRID];
    float d1 = (r1 < CGRID) ? (float)r1 : (float)g_ovfB[r1 - CGRID];

    uint32_t Ahi[16], Alo[16];
#pragma unroll
    for (int kc = 0; kc < 4; kc++) {
        int c0 = kc * 16 + 2 * t;
#pragma unroll
        for (int half = 0; half < 2; half++) {
            int c = c0 + half * 8;
            float p0 = sv[c],     u0 = sv[64 + c];
            float p1 = sv[c + 1], u1 = sv[64 + c + 1];
            float h00 = fmaxf(p0 + d0 * u0, 0.f);
            float h01 = fmaxf(p1 + d0 * u1, 0.f);
            float h10 = fmaxf(p0 + d1 * u0, 0.f);
            float h11 = fmaxf(p1 + d1 * u1, 0.f);
            pack_hl(h00, h01, Ahi[kc * 4 + half * 2 + 0], Alo[kc * 4 + half * 2 + 0]);
            pack_hl(h10, h11, Ahi[kc * 4 + half * 2 + 1], Alo[kc * 4 + half * 2 + 1]);
        }
    }

    float acc[8][4], acc2[8][4];
    uint32_t A2hi[16], A2lo[16];

#pragma unroll
    for (int nt = 0; nt < 8; nt++) { acc[nt][0]=0.f; acc[nt][1]=0.f; acc[nt][2]=0.f; acc[nt][3]=0.f; }
    gemm_tile(acc, Ahi, Alo, sm + 1 * 2 * 64 * AS, g, t);
    store_tile(acc, bnB1, g_TzB, row0, row1, limit, t);

#pragma unroll
    for (int nt = 0; nt < 8; nt++) { acc[nt][0]=0.f; acc[nt][1]=0.f; acc[nt][2]=0.f; acc[nt][3]=0.f; }
    gemm_tile(acc, Ahi, Alo, sm, g, t);
    c2a(acc, bba1, A2hi, A2lo, t);
#pragma unroll
    for (int nt = 0; nt < 8; nt++) { acc2[nt][0]=0.f; acc2[nt][1]=0.f; acc2[nt][2]=0.f; acc2[nt][3]=0.f; }
    gemm_tile(acc2, A2hi, A2lo, sm + 2 * 2 * 64 * AS, g, t);
    store_tile(acc2, nullptr, g_Tba, row0, row1, limit, t);
}

// ======================= fused gather (dual-cid float4) =======================
// Warp owns one row. Lanes 0-15 accumulate even-indexed cids, lanes 16-31 odd;
// each lane holds float4 columns [j*4, j*4+4). One shfl + one LDG.128 per 2 cids.
__device__ __forceinline__ void seg_sum4(float4& s, int b, int e,
                                         const float* __restrict__ T,
                                         int lane, int j, int half) {
    int cnt = e - b;
    for (int base = 0; base < cnt; base += 32) {
        int m = min(cnt - base, 32);
        int idx = (lane < m) ? __ldg(&g_csr[b + base + lane]) : 0;
        int iters = (m + 1) >> 1;
        for (int k = 0; k < iters; k++) {
            int srcl = 2 * k + half;
            int c = __shfl_sync(0xffffffffu, idx, srcl);
            if (srcl < m) {
                float4 p = *reinterpret_cast<const float4*>(T + (size_t)c * 64 + j * 4);
                s.x += p.x; s.y += p.y; s.z += p.z; s.w += p.w;
            }
        }
    }
}

__global__ void __launch_bounds__(256) k_gather(float* __restrict__ out) {
    int row = blockIdx.x * 8 + (threadIdx.x >> 5);
    if (row >= NA + NB) return;
    int lane = threadIdx.x & 31;
    int j = lane & 15, half = lane >> 4;
    float4 s = make_float4(0.f, 0.f, 0.f, 0.f);
    if (row < NA) {
        int cself = __ldg(&g_cidA[row]);
        if (half == 0)
            s = *reinterpret_cast<const float4*>(g_TzA + (size_t)cself * 64 + j * 4);
        seg_sum4(s, g_off[row],      g_off[row + 1],      g_Taa, lane, j, half);
        seg_sum4(s, g_off[NA + row], g_off[NA + row + 1], g_Tba, lane, j, half);
    } else {
        int rb = row - NA;
        int cself = __ldg(&g_cidB[rb]);
        if (half == 0)
            s = *reinterpret_cast<const float4*>(g_TzB + (size_t)cself * 64 + j * 4);
        seg_sum4(s, g_off[2 * NA + rb], g_off[2 * NA + rb + 1], g_Tab, lane, j, half);
    }
    // merge the two half-warp partial sums
    s.x += __shfl_xor_sync(0xffffffffu, s.x, 16);
    s.y += __shfl_xor_sync(0xffffffffu, s.y, 16);
    s.z += __shfl_xor_sync(0xffffffffu, s.z, 16);
    s.w += __shfl_xor_sync(0xffffffffu, s.w, 16);
    s.x = fmaxf(s.x, 0.f); s.y = fmaxf(s.y, 0.f);
    s.z = fmaxf(s.z, 0.f); s.w = fmaxf(s.w, 0.f);
    if (half == 0)
        *reinterpret_cast<float4*>(out + (size_t)row * 64 + j * 4) = s;
}

// ==============================================================================
struct Aux {
    cudaStream_t s2;
    cudaEvent_t evF, evS, evJ, evG, evZ;
    Aux() {
        cudaStreamCreateWithFlags(&s2, cudaStreamNonBlocking);
        cudaEventCreateWithFlags(&evF, cudaEventDisableTiming);
        cudaEventCreateWithFlags(&evS, cudaEventDisableTiming);
        cudaEventCreateWithFlags(&evJ, cudaEventDisableTiming);
        cudaEventCreateWithFlags(&evG, cudaEventDisableTiming);
        cudaEventCreateWithFlags(&evZ, cudaEventDisableTiming);
    }
};

extern "C" void kernel_launch(void* const* d_in, const int* in_sizes, int n_in,
                              void* d_out, int out_size) {
    static Aux aux;

    const int*   src_aa = (const int*)d_in[0];
    const int*   dst_aa = (const int*)d_in[1];
    const int*   src_ab = (const int*)d_in[2];
    const int*   dst_ab = (const int*)d_in[3];
    const int*   src_ba = (const int*)d_in[4];
    const int*   dst_ba = (const int*)d_in[5];
    const float* embA   = (const float*)d_in[6];
    const float* embB   = (const float*)d_in[7];
    const float* Waa    = (const float*)d_in[8];
    const float* baa    = (const float*)d_in[9];
    const float* Wab    = (const float*)d_in[10];
    const float* bab    = (const float*)d_in[11];
    const float* Wba    = (const float*)d_in[12];
    const float* bba    = (const float*)d_in[13];
    const float* WnA    = (const float*)d_in[14];
    const float* bnA    = (const float*)d_in[15];
    const float* WnB    = (const float*)d_in[16];
    const float* bnB    = (const float*)d_in[17];
    const int Eaa = in_sizes[0];
    const int Eab = in_sizes[2];
    const int Eba = in_sizes[4];
    const int Etot = Eaa + Eba + Eab;
    float* out = (float*)d_out;

    cudaFuncSetAttribute(k_gemmA, cudaFuncAttributeMaxDynamicSharedMemorySize, SMEM_A_BYTES);
    cudaFuncSetAttribute(k_gemmB, cudaFuncAttributeMaxDynamicSharedMemorySize, SMEM_B_BYTES);

    const float* Waa1 = Waa + 4096;
    const float* Wab1 = Wab + 4096;
    const float* Wba1 = Wba + 4096;
    const float* baa1 = baa + 64;
    const float* bab1 = bab + 64;
    const float* bba1 = bba + 64;
    const float* WnA1 = WnA + 192 * 64;
    const float* WnB1 = WnB + 128 * 64;
    const float* bnA1 = bnA + 64;
    const float* bnB1 = bnB + 64;

    // fork: combo-grid GEMMs depend only on weights -> side stream
    cudaEventRecord(aux.evF, 0);
    cudaStreamWaitEvent(aux.s2, aux.evF, 0);
    k_gemmA<<<CGRID / 128, 256, SMEM_A_BYTES, aux.s2>>>(
        embA, embB, Waa, baa, Wba, bba, WnA, bnA,
        Waa1, baa1, Wab1, bab1, WnA1, bnA1, WnB1 + 4096, 0);
    k_gemmB<<<CGRID / 128, 256, SMEM_B_BYTES, aux.s2>>>(
        embA, embB, Wab, bab, WnB, bnB,
        Wba1, bba1, WnB1, bnB1, WnA1 + 2 * 4096, 0);

    // main chain: deg -> single-pass scan+cid
    k_deg_all<<<(Etot + 255) / 256, 256>>>(dst_aa, Eaa, dst_ba, Eba, dst_ab, Eab);
    k_scan_cid<<<SCAN_NBLK, 1024>>>();

    // side stream after scan: overflow GEMM rows (evJ)
    cudaEventRecord(aux.evS, 0);
    cudaStreamWaitEvent(aux.s2, aux.evS, 0);
    k_gemmA<<<(NA + 127) / 128, 256, SMEM_A_BYTES, aux.s2>>>(
        embA, embB, Waa, baa, Wba, bba, WnA, bnA,
        Waa1, baa1, Wab1, bab1, WnA1, bnA1, WnB1 + 4096, 1);
    k_gemmB<<<(NB + 127) / 128, 256, SMEM_B_BYTES, aux.s2>>>(
        embA, embB, Wab, bab, WnB, bnB,
        Wba1, bba1, WnB1, bnB1, WnA1 + 2 * 4096, 1);
    cudaEventRecord(aux.evJ, aux.s2);

    k_fill_all<<<(Etot + 255) / 256, 256>>>(src_aa, dst_aa, Eaa,
                                            src_ba, dst_ba, Eba,
                                            src_ab, dst_ab, Eab);

    // join tables; then gather on main while zero_end runs on s2 concurrently
    cudaStreamWaitEvent(0, aux.evJ, 0);
    cudaEventRecord(aux.evG, 0);              // after fill + tables
    cudaStreamWaitEvent(aux.s2, aux.evG, 0);
    k_gather<<<(NA + NB + 7) / 8, 256>>>(out);
    k_zero_end<<<(NTOT / 4 + 255) / 256, 256, 0, aux.s2>>>();
    cudaEventRecord(aux.evZ, aux.s2);
    cudaStreamWaitEvent(0, aux.evZ, 0);       // full join before capture end
}

// round 12
// speedup vs baseline: 1.0026x; 1.0026x over previous
#include <cuda_runtime.h>
#include <cuda_bf16.h>
#include <cstdint>

#define NA 100000
#define NB 100000
#define D 64
#define NTOT (NA + NA + NB)                 // deg/off layout: [aa->A | ba->A | ab->B]
#define ECAP 2000000
#define AS 72                               // smem row stride (bf16), conflict-free
#define CGRID 4096                          // 64x64 degree-pair grid (A); 1-D for B
#define TROWSA (CGRID + NA)
#define TROWSB (CGRID + NB)
#define SCAN_NBLK ((NTOT + 1023) / 1024)    // 293

// ======================= scratch (zero-initialized at module load) ===========
__device__ int      g_deg[NTOT];            // zeroed at end of every run
__device__ unsigned g_state[SCAN_NBLK];     // scan lookback state; zeroed at end
__device__ int      g_novf[2];              // overflow counters; zeroed at end
__device__ int      g_off[NTOT + 1];
__device__ int      g_cur[NTOT];
__device__ int      g_csr[ECAP];            // combo-id of src, grouped by dst
__device__ int      g_cidA[NA];
__device__ int      g_cidB[NB];
__device__ int2     g_ovfA[NA];
__device__ int      g_ovfB[NB];
__device__ float    g_TzA[TROWSA * D];
__device__ float    g_Taa[TROWSA * D];
__device__ float    g_Tab[TROWSA * D];
__device__ float    g_TzB[TROWSB * D];
__device__ float    g_Tba[TROWSB * D];

// ======================= sparse machinery ====================================
__global__ void k_deg_all(const int* __restrict__ d_aa, int Eaa,
                          const int* __restrict__ d_ba, int Eba,
                          const int* __restrict__ d_ab, int Eab) {
    int i = blockIdx.x * blockDim.x + threadIdx.x;
    if (i < Eaa) {
        atomicAdd(&g_deg[d_aa[i]], 1);
    } else if (i < Eaa + Eba) {
        atomicAdd(&g_deg[NA + d_ba[i - Eaa]], 1);
    } else if (i < Eaa + Eba + Eab) {
        atomicAdd(&g_deg[2 * NA + d_ab[i - Eaa - Eba]], 1);
    }
}

// single-pass decoupled-lookback exclusive scan (WARP-PARALLEL lookback)
// + combo-id assignment. All SCAN_NBLK blocks simultaneously resident.
__global__ void __launch_bounds__(1024) k_scan_cid() {
    __shared__ int wsum[32];
    __shared__ int s_total, s_prefix;
    int b = blockIdx.x, t = threadIdx.x;
    int i = b * 1024 + t;
    int v = (i < NTOT) ? g_deg[i] : 0;
    int x = v;
#pragma unroll
    for (int o = 1; o < 32; o <<= 1) {
        int y = __shfl_up_sync(0xffffffffu, x, o);
        if ((t & 31) >= o) x += y;
    }
    if ((t & 31) == 31) wsum[t >> 5] = x;
    __syncthreads();
    if (t < 32) {
        int w = wsum[t];
        int xx = w;
#pragma unroll
        for (int o = 1; o < 32; o <<= 1) {
            int y = __shfl_up_sync(0xffffffffu, xx, o);
            if (t >= o) xx += y;
        }
        wsum[t] = xx - w;
        if (t == 31) {
            s_total = xx;
            unsigned st = ((b == 0 ? 2u : 1u) << 30) | (unsigned)xx;
            atomicExch(&g_state[b], st);
        }
    }
    __syncthreads();
    int excl = x - v + wsum[t >> 5];

    // warp-parallel lookback by warp 0
    if (t < 32) {
        int pref = 0;
        if (b > 0) {
            int j = b - 1;
            while (true) {
                int idx = j - t;                      // lane 0 = nearest predecessor
                unsigned st;
                do {
                    st = (idx >= 0) ? atomicAdd(&g_state[idx], 0u) : (2u << 30);
                } while (__any_sync(0xffffffffu, (st >> 30) == 0));
                unsigned incmask = __ballot_sync(0xffffffffu, (st >> 30) >= 2);
                int firstInc = __ffs(incmask) - 1;    // closest inclusive in window
                int val = (int)(st & 0x3FFFFFFFu);
                int take = (firstInc >= 0) ? ((t <= firstInc) ? val : 0) : val;
#pragma unroll
                for (int o = 16; o; o >>= 1) take += __shfl_down_sync(0xffffffffu, take, o);
                take = __shfl_sync(0xffffffffu, take, 0);
                pref += take;
                if (firstInc >= 0) break;
                j -= 32;
            }
            if (t == 0) atomicExch(&g_state[b], (2u << 30) | (unsigned)(pref + s_total));
        }
        if (t == 0) s_prefix = pref;
    }
    __syncthreads();
    int off = s_prefix + excl;
    if (i < NTOT) { g_off[i] = off; g_cur[i] = off; }
    if (i == NTOT - 1) g_off[NTOT] = off + v;

    // combo-id assignment
    if (i < NA) {
        int d1 = v, d2 = g_deg[NA + i];
        int cid;
        if (d1 < 64 && d2 < 64) cid = d1 * 64 + d2;
        else { int o = atomicAdd(&g_novf[0], 1); g_ovfA[o] = make_int2(d1, d2); cid = CGRID + o; }
        g_cidA[i] = cid;
    } else if (i < NA + NB) {
        int d = g_deg[NA + i];              // == g_deg[2*NA + (i-NA)]
        int cid;
        if (d < CGRID) cid = d;
        else { int o = atomicAdd(&g_novf[1], 1); g_ovfB[o] = d; cid = CGRID + o; }
        g_cidB[i - NA] = cid;
    }
}

// counting-sort fill; stores the SRC COMBO-ID
__global__ void k_fill_all(const int* __restrict__ s_aa, const int* __restrict__ d_aa, int Eaa,
                           const int* __restrict__ s_ba, const int* __restrict__ d_ba, int Eba,
                           const int* __restrict__ s_ab, const int* __restrict__ d_ab, int Eab) {
    int i = blockIdx.x * blockDim.x + threadIdx.x;
    int cid, base, dstv;
    if (i < Eaa) { cid = __ldg(&g_cidA[s_aa[i]]); dstv = d_aa[i]; base = 0; }
    else if (i < Eaa + Eba) { int j = i - Eaa; cid = __ldg(&g_cidB[s_ba[j]]); dstv = d_ba[j]; base = NA; }
    else if (i < Eaa + Eba + Eab) { int j = i - Eaa - Eba; cid = __ldg(&g_cidA[s_ab[j]]); dstv = d_ab[j]; base = 2 * NA; }
    else return;
    int pos = atomicAdd(&g_cur[base + dstv], 1);
    g_csr[pos] = cid;
}

// zero scratch at END of run (module load provides the initial zeros)
__global__ void k_zero_end() {
    int i = blockIdx.x * blockDim.x + threadIdx.x;
    if (i < NTOT / 4) reinterpret_cast<int4*>(g_deg)[i] = make_int4(0, 0, 0, 0);
    if (i < SCAN_NBLK) g_state[i] = 0;
    if (i == 0) { g_novf[0] = 0; g_novf[1] = 0; }
}

// ======================= MMA helpers =========================================
__device__ __forceinline__ void mma_bf16(float c[4], const uint32_t a[4],
                                         uint32_t b0, uint32_t b1) {
    asm volatile("mma.sync.aligned.m16n8k16.row.col.f32.bf16.bf16.f32 "
                 "{%0,%1,%2,%3}, {%4,%5,%6,%7}, {%8,%9}, {%0,%1,%2,%3};"
                 : "+f"(c[0]), "+f"(c[1]), "+f"(c[2]), "+f"(c[3])
                 : "r"(a[0]), "r"(a[1]), "r"(a[2]), "r"(a[3]), "r"(b0), "r"(b1));
}
__device__ __forceinline__ void pack_hl(float x, float y, uint32_t& hi, uint32_t& lo) {
    __nv_bfloat162 H, L;
    H.x = __float2bfloat16(x); H.y = __float2bfloat16(y);
    L.x = __float2bfloat16(x - __bfloat162float(H.x));
    L.y = __float2bfloat16(y - __bfloat162float(H.y));
    hi = *reinterpret_cast<uint32_t*>(&H);
    lo = *reinterpret_cast<uint32_t*>(&L);
}
__device__ __forceinline__ void gemm_tile(float acc[8][4],
                                          const uint32_t* Ahi, const uint32_t* Alo,
                                          const __nv_bfloat16* whi, int g, int t) {
    const __nv_bfloat16* wlo = whi + 64 * AS;
#pragma unroll
    for (int nt = 0; nt < 8; nt++) {
        const __nv_bfloat16* bh = whi + (nt * 8 + g) * AS + 2 * t;
        const __nv_bfloat16* bl = wlo + (nt * 8 + g) * AS + 2 * t;
#pragma unroll
        for (int kc = 0; kc < 4; kc++) {
            uint32_t bh0 = *reinterpret_cast<const uint32_t*>(bh + kc * 16);
            uint32_t bh1 = *reinterpret_cast<const uint32_t*>(bh + kc * 16 + 8);
            uint32_t bl0 = *reinterpret_cast<const uint32_t*>(bl + kc * 16);
            uint32_t bl1 = *reinterpret_cast<const uint32_t*>(bl + kc * 16 + 8);
            mma_bf16(acc[nt], &Ahi[kc * 4], bh0, bh1);
            mma_bf16(acc[nt], &Ahi[kc * 4], bl0, bl1);
            mma_bf16(acc[nt], &Alo[kc * 4], bh0, bh1);
        }
    }
}
__device__ __forceinline__ void c2a(float acc[8][4], const float* __restrict__ bias,
                                    uint32_t A2hi[16], uint32_t A2lo[16], int t) {
#pragma unroll
    for (int kc = 0; kc < 4; kc++) {
        int nt0 = 2 * kc, nt1 = nt0 + 1;
        float b00 = __ldg(bias + nt0 * 8 + 2 * t), b01 = __ldg(bias + nt0 * 8 + 2 * t + 1);
        float b10 = __ldg(bias + nt1 * 8 + 2 * t), b11 = __ldg(bias + nt1 * 8 + 2 * t + 1);
        float x0 = fmaxf(acc[nt0][0] + b00, 0.f), x1 = fmaxf(acc[nt0][1] + b01, 0.f);
        float x2 = fmaxf(acc[nt0][2] + b00, 0.f), x3 = fmaxf(acc[nt0][3] + b01, 0.f);
        float y0 = fmaxf(acc[nt1][0] + b10, 0.f), y1 = fmaxf(acc[nt1][1] + b11, 0.f);
        float y2 = fmaxf(acc[nt1][2] + b10, 0.f), y3 = fmaxf(acc[nt1][3] + b11, 0.f);
        pack_hl(x0, x1, A2hi[kc * 4 + 0], A2lo[kc * 4 + 0]);
        pack_hl(x2, x3, A2hi[kc * 4 + 1], A2lo[kc * 4 + 1]);
        pack_hl(y0, y1, A2hi[kc * 4 + 2], A2lo[kc * 4 + 2]);
        pack_hl(y2, y3, A2hi[kc * 4 + 3], A2lo[kc * 4 + 3]);
    }
}
__device__ __forceinline__ void store_tile(float acc[8][4], const float* __restrict__ bias,
                                           float* __restrict__ out, int row0, int row1,
                                           int R, int t) {
#pragma unroll
    for (int nt = 0; nt < 8; nt++) {
        int col = nt * 8 + 2 * t;
        float bx = bias ? __ldg(bias + col) : 0.f;
        float by = bias ? __ldg(bias + col + 1) : 0.f;
        float2 v0 = make_float2(acc[nt][0] + bx, acc[nt][1] + by);
        float2 v1 = make_float2(acc[nt][2] + bx, acc[nt][3] + by);
        if (row0 < R) *reinterpret_cast<float2*>(out + (size_t)row0 * 64 + col) = v0;
        if (row1 < R) *reinterpret_cast<float2*>(out + (size_t)row1 * 64 + col) = v1;
    }
}
__device__ __forceinline__ void stage_w(__nv_bfloat16* sm, const float* const* wsrc,
                                        int nm, int tid) {
    for (int m = 0; m < nm; m++) {
        const float* w = wsrc[m];
        __nv_bfloat16* whi = sm + m * 2 * 64 * AS;
        __nv_bfloat16* wlo = whi + 64 * AS;
        for (int i = tid; i < 4096; i += 256) {
            int k = i >> 6, n = i & 63;
            float x = w[i];
            __nv_bfloat16 hi = __float2bfloat16(x);
            whi[n * AS + k] = hi;
            wlo[n * AS + k] = __float2bfloat16(x - __bfloat162float(hi));
        }
    }
}

// ======================= combo-table GEMM kernels =============================
#define SMEM_A_BYTES (5 * 2 * 64 * AS * 2)   // 92160
__global__ void __launch_bounds__(256) k_gemmA(
        const float* __restrict__ embA, const float* __restrict__ embB,
        const float* __restrict__ Waa0, const float* __restrict__ baa0,
        const float* __restrict__ Wba0, const float* __restrict__ bba0,
        const float* __restrict__ WnA0, const float* __restrict__ bnA0,
        const float* __restrict__ Waa1, const float* __restrict__ baa1,
        const float* __restrict__ Wab1, const float* __restrict__ bab1,
        const float* __restrict__ WnA1, const float* __restrict__ bnA1,
        const float* __restrict__ WnB1blk1, int is_ovf) {
    int row_off = is_ovf ? CGRID : 0;
    int nrows   = is_ovf ? g_novf[0] : CGRID;
    if ((int)blockIdx.x * 128 >= nrows) return;
    int limit = row_off + nrows;

    extern __shared__ __nv_bfloat16 sm[];
    __shared__ float sA[64], sB[64], v1[64], v2[64], sv[192];
    int tid = threadIdx.x;
    const float* wsrc[5] = { Waa1, Wab1, WnA1, WnA1 + 4096, WnB1blk1 };
    stage_w(sm, wsrc, 5, tid);
    if (tid < 64) { sA[tid] = embA[tid]; sB[tid] = embB[tid]; }
    __syncthreads();
    if (tid < 64) {
        int c = tid;
        float a0 = baa0[c], a2 = bba0[c];
        for (int k = 0; k < 64; k++) {
            a0 += sA[k] * Waa0[k * 64 + c];
            a2 += sB[k] * Wba0[k * 64 + c];
        }
        v1[c] = fmaxf(a0, 0.f); v2[c] = fmaxf(a2, 0.f);
    }
    __syncthreads();
    if (tid < 64) {
        int c = tid;
        float cA = bnA0[c], uaa = 0.f, uba = 0.f;
        for (int k = 0; k < 64; k++) {
            cA  += sA[k] * WnA0[k * 64 + c];
            uaa += v1[k] * WnA0[(64 + k) * 64 + c];
            uba += v2[k] * WnA0[(128 + k) * 64 + c];
        }
        sv[c] = cA; sv[64 + c] = uaa; sv[128 + c] = uba;
    }
    __syncthreads();

    int lane = tid & 31, wid = tid >> 5;
    int g = lane >> 2, t = lane & 3;
    int row0 = row_off + blockIdx.x * 128 + wid * 16 + g, row1 = row0 + 8;
    int r0 = min(row0, limit - 1), r1 = min(row1, limit - 1);
    float d10, d20, d11, d21;
    if (r0 < CGRID) { d10 = (float)(r0 >> 6); d20 = (float)(r0 & 63); }
    else { int2 dd = g_ovfA[r0 - CGRID]; d10 = (float)dd.x; d20 = (float)dd.y; }
    if (r1 < CGRID) { d11 = (float)(r1 >> 6); d21 = (float)(r1 & 63); }
    else { int2 dd = g_ovfA[r1 - CGRID]; d11 = (float)dd.x; d21 = (float)dd.y; }

    uint32_t Ahi[16], Alo[16];
#pragma unroll
    for (int kc = 0; kc < 4; kc++) {
        int c0 = kc * 16 + 2 * t;
#pragma unroll
        for (int half = 0; half < 2; half++) {
            int c = c0 + half * 8;
            float p0 = sv[c],     u0 = sv[64 + c],     w0 = sv[128 + c];
            float p1 = sv[c + 1], u1 = sv[64 + c + 1], w1 = sv[128 + c + 1];
            float h00 = fmaxf(p0 + d10 * u0 + d20 * w0, 0.f);
            float h01 = fmaxf(p1 + d10 * u1 + d20 * w1, 0.f);
            float h10 = fmaxf(p0 + d11 * u0 + d21 * w0, 0.f);
            float h11 = fmaxf(p1 + d11 * u1 + d21 * w1, 0.f);
            pack_hl(h00, h01, Ahi[kc * 4 + half * 2 + 0], Alo[kc * 4 + half * 2 + 0]);
            pack_hl(h10, h11, Ahi[kc * 4 + half * 2 + 1], Alo[kc * 4 + half * 2 + 1]);
        }
    }

    float acc[8][4], acc2[8][4];
    uint32_t A2hi[16], A2lo[16];

#pragma unroll
    for (int nt = 0; nt < 8; nt++) { acc[nt][0]=0.f; acc[nt][1]=0.f; acc[nt][2]=0.f; acc[nt][3]=0.f; }
    gemm_tile(acc, Ahi, Alo, sm + 2 * 2 * 64 * AS, g, t);
    store_tile(acc, bnA1, g_TzA, row0, row1, limit, t);

#pragma unroll
    for (int nt = 0; nt < 8; nt++) { acc[nt][0]=0.f; acc[nt][1]=0.f; acc[nt][2]=0.f; acc[nt][3]=0.f; }
    gemm_tile(acc, Ahi, Alo, sm, g, t);
    c2a(acc, baa1, A2hi, A2lo, t);
#pragma unroll
    for (int nt = 0; nt < 8; nt++) { acc2[nt][0]=0.f; acc2[nt][1]=0.f; acc2[nt][2]=0.f; acc2[nt][3]=0.f; }
    gemm_tile(acc2, A2hi, A2lo, sm + 3 * 2 * 64 * AS, g, t);
    store_tile(acc2, nullptr, g_Taa, row0, row1, limit, t);

#pragma unroll
    for (int nt = 0; nt < 8; nt++) { acc[nt][0]=0.f; acc[nt][1]=0.f; acc[nt][2]=0.f; acc[nt][3]=0.f; }
    gemm_tile(acc, Ahi, Alo, sm + 1 * 2 * 64 * AS, g, t);
    c2a(acc, bab1, A2hi, A2lo, t);
#pragma unroll
    for (int nt = 0; nt < 8; nt++) { acc2[nt][0]=0.f; acc2[nt][1]=0.f; acc2[nt][2]=0.f; acc2[nt][3]=0.f; }
    gemm_tile(acc2, A2hi, A2lo, sm + 4 * 2 * 64 * AS, g, t);
    store_tile(acc2, nullptr, g_Tab, row0, row1, limit, t);
}

#define SMEM_B_BYTES (3 * 2 * 64 * AS * 2)   // 55296
__global__ void __launch_bounds__(256) k_gemmB(
        const float* __restrict__ embA, const float* __restrict__ embB,
        const float* __restrict__ Wab0, const float* __restrict__ bab0,
        const float* __restrict__ WnB0, const float* __restrict__ bnB0,
        const float* __restrict__ Wba1, const float* __restrict__ bba1,
        const float* __restrict__ WnB1, const float* __restrict__ bnB1,
        const float* __restrict__ WnA1blk2, int is_ovf) {
    int row_off = is_ovf ? CGRID : 0;
    int nrows   = is_ovf ? g_novf[1] : CGRID;
    if ((int)blockIdx.x * 128 >= nrows) return;
    int limit = row_off + nrows;

    extern __shared__ __nv_bfloat16 sm[];
    __shared__ float sA[64], sB[64], v1[64], sv[128];
    int tid = threadIdx.x;
    const float* wsrc[3] = { Wba1, WnB1, WnA1blk2 };
    stage_w(sm, wsrc, 3, tid);
    if (tid < 64) { sA[tid] = embA[tid]; sB[tid] = embB[tid]; }
    __syncthreads();
    if (tid < 64) {
        int c = tid;
        float a1 = bab0[c];
        for (int k = 0; k < 64; k++) a1 += sA[k] * Wab0[k * 64 + c];
        v1[c] = fmaxf(a1, 0.f);
    }
    __syncthreads();
    if (tid < 64) {
        int c = tid;
        float cB = bnB0[c], uab = 0.f;
        for (int k = 0; k < 64; k++) {
            cB  += sB[k] * WnB0[k * 64 + c];
            uab += v1[k] * WnB0[(64 + k) * 64 + c];
        }
        sv[c] = cB; sv[64 + c] = uab;
    }
    __syncthreads();

    int lane = tid & 31, wid = tid >> 5;
    int g = lane >> 2, t = lane & 3;
    int row0 = row_off + blockIdx.x * 128 + wid * 16 + g, row1 = row0 + 8;
    int r0 = min(row0, limit - 1), r1 = min(row1, limit - 1);
    float d0 = (r0 < CGRID) ? (float)r0 : (float)g_ovfB[r0 - CGRID];
    float d1 = (r1 < CGRID) ? (float)r1 : (float)g_ovfB[r1 - CGRID];

    uint32_t Ahi[16], Alo[16];
#pragma unroll
    for (int kc = 0; kc < 4; kc++) {
        int c0 = kc * 16 + 2 * t;
#pragma unroll
        for (int half = 0; half < 2; half++) {
            int c = c0 + half * 8;
            float p0 = sv[c],     u0 = sv[64 + c];
            float p1 = sv[c + 1], u1 = sv[64 + c + 1];
            float h00 = fmaxf(p0 + d0 * u0, 0.f);
            float h01 = fmaxf(p1 + d0 * u1, 0.f);
            float h10 = fmaxf(p0 + d1 * u0, 0.f);
            float h11 = fmaxf(p1 + d1 * u1, 0.f);
            pack_hl(h00, h01, Ahi[kc * 4 + half * 2 + 0], Alo[kc * 4 + half * 2 + 0]);
            pack_hl(h10, h11, Ahi[kc * 4 + half * 2 + 1], Alo[kc * 4 + half * 2 + 1]);
        }
    }

    float acc[8][4], acc2[8][4];
    uint32_t A2hi[16], A2lo[16];

#pragma unroll
    for (int nt = 0; nt < 8; nt++) { acc[nt][0]=0.f; acc[nt][1]=0.f; acc[nt][2]=0.f; acc[nt][3]=0.f; }
    gemm_tile(acc, Ahi, Alo, sm + 1 * 2 * 64 * AS, g, t);
    store_tile(acc, bnB1, g_TzB, row0, row1, limit, t);

#pragma unroll
    for (int nt = 0; nt < 8; nt++) { acc[nt][0]=0.f; acc[nt][1]=0.f; acc[nt][2]=0.f; acc[nt][3]=0.f; }
    gemm_tile(acc, Ahi, Alo, sm, g, t);
    c2a(acc, bba1, A2hi, A2lo, t);
#pragma unroll
    for (int nt = 0; nt < 8; nt++) { acc2[nt][0]=0.f; acc2[nt][1]=0.f; acc2[nt][2]=0.f; acc2[nt][3]=0.f; }
    gemm_tile(acc2, A2hi, A2lo, sm + 2 * 2 * 64 * AS, g, t);
    store_tile(acc2, nullptr, g_Tba, row0, row1, limit, t);
}

// ======================= fused gather =========================================
__device__ __forceinline__ void seg_sum(float2& s, int b, int e,
                                        const float* __restrict__ T, int lane) {
    int cnt = e - b;
    for (int base = 0; base < cnt; base += 32) {
        int rem = cnt - base;
        int m = rem < 32 ? rem : 32;
        int idx = (lane < m) ? __ldg(&g_csr[b + base + lane]) : 0;
        int k = 0;
        for (; k + 1 < m; k += 2) {
            int c0 = __shfl_sync(0xffffffffu, idx, k);
            int c1 = __shfl_sync(0xffffffffu, idx, k + 1);
            float2 p = *reinterpret_cast<const float2*>(T + (size_t)c0 * 64 + lane * 2);
            float2 q = *reinterpret_cast<const float2*>(T + (size_t)c1 * 64 + lane * 2);
            s.x += p.x + q.x; s.y += p.y + q.y;
        }
        if (k < m) {
            int c0 = __shfl_sync(0xffffffffu, idx, k);
            float2 p = *reinterpret_cast<const float2*>(T + (size_t)c0 * 64 + lane * 2);
            s.x += p.x; s.y += p.y;
        }
    }
}

__global__ void __launch_bounds__(256) k_gather(float* __restrict__ out) {
    int row = blockIdx.x * 8 + (threadIdx.x >> 5);
    if (row >= NA + NB) return;
    int lane = threadIdx.x & 31;
    float2 s;
    if (row < NA) {
        int cself = __ldg(&g_cidA[row]);
        s = *reinterpret_cast<const float2*>(g_TzA + (size_t)cself * 64 + lane * 2);
        seg_sum(s, g_off[row],      g_off[row + 1],      g_Taa, lane);
        seg_sum(s, g_off[NA + row], g_off[NA + row + 1], g_Tba, lane);
    } else {
        int rb = row - NA;
        int cself = __ldg(&g_cidB[rb]);
        s = *reinterpret_cast<const float2*>(g_TzB + (size_t)cself * 64 + lane * 2);
        seg_sum(s, g_off[2 * NA + rb], g_off[2 * NA + rb + 1], g_Tab, lane);
    }
    s.x = fmaxf(s.x, 0.f); s.y = fmaxf(s.y, 0.f);
    *reinterpret_cast<float2*>(out + (size_t)row * 64 + lane * 2) = s;
}

// ==============================================================================
struct Aux {
    cudaStream_t s2;
    cudaEvent_t evF, evS, evJ;
    Aux() {
        cudaStreamCreateWithFlags(&s2, cudaStreamNonBlocking);
        cudaEventCreateWithFlags(&evF, cudaEventDisableTiming);
        cudaEventCreateWithFlags(&evS, cudaEventDisableTiming);
        cudaEventCreateWithFlags(&evJ, cudaEventDisableTiming);
    }
};

extern "C" void kernel_launch(void* const* d_in, const int* in_sizes, int n_in,
                              void* d_out, int out_size) {
    static Aux aux;   // stream/events created once (outside capture on first call)

    const int*   src_aa = (const int*)d_in[0];
    const int*   dst_aa = (const int*)d_in[1];
    const int*   src_ab = (const int*)d_in[2];
    const int*   dst_ab = (const int*)d_in[3];
    const int*   src_ba = (const int*)d_in[4];
    const int*   dst_ba = (const int*)d_in[5];
    const float* embA   = (const float*)d_in[6];
    const float* embB   = (const float*)d_in[7];
    const float* Waa    = (const float*)d_in[8];
    const float* baa    = (const float*)d_in[9];
    const float* Wab    = (const float*)d_in[10];
    const float* bab    = (const float*)d_in[11];
    const float* Wba    = (const float*)d_in[12];
    const float* bba    = (const float*)d_in[13];
    const float* WnA    = (const float*)d_in[14];
    const float* bnA    = (const float*)d_in[15];
    const float* WnB    = (const float*)d_in[16];
    const float* bnB    = (const float*)d_in[17];
    const int Eaa = in_sizes[0];
    const int Eab = in_sizes[2];
    const int Eba = in_sizes[4];
    const int Etot = Eaa + Eba + Eab;
    float* out = (float*)d_out;

    cudaFuncSetAttribute(k_gemmA, cudaFuncAttributeMaxDynamicSharedMemorySize, SMEM_A_BYTES);
    cudaFuncSetAttribute(k_gemmB, cudaFuncAttributeMaxDynamicSharedMemorySize, SMEM_B_BYTES);

    const float* Waa1 = Waa + 4096;
    const float* Wab1 = Wab + 4096;
    const float* Wba1 = Wba + 4096;
    const float* baa1 = baa + 64;
    const float* bab1 = bab + 64;
    const float* bba1 = bba + 64;
    const float* WnA1 = WnA + 192 * 64;
    const float* WnB1 = WnB + 128 * 64;
    const float* bnA1 = bnA + 64;
    const float* bnB1 = bnB + 64;

    // fork: combo-grid GEMMs depend only on weights -> side stream
    cudaEventRecord(aux.evF, 0);
    cudaStreamWaitEvent(aux.s2, aux.evF, 0);
    k_gemmA<<<CGRID / 128, 256, SMEM_A_BYTES, aux.s2>>>(
        embA, embB, Waa, baa, Wba, bba, WnA, bnA,
        Waa1, baa1, Wab1, bab1, WnA1, bnA1, WnB1 + 4096, 0);
    k_gemmB<<<CGRID / 128, 256, SMEM_B_BYTES, aux.s2>>>(
        embA, embB, Wab, bab, WnB, bnB,
        Wba1, bba1, WnB1, bnB1, WnA1 + 2 * 4096, 0);

    // main chain: deg -> single-pass scan+cid (warp-parallel lookback)
    k_deg_all<<<(Etot + 255) / 256, 256>>>(dst_aa, Eaa, dst_ba, Eba, dst_ab, Eab);
    k_scan_cid<<<SCAN_NBLK, 1024>>>();

    // overflow GEMM rows (depend on scan) on side stream, concurrent with fill
    cudaEventRecord(aux.evS, 0);
    cudaStreamWaitEvent(aux.s2, aux.evS, 0);
    k_gemmA<<<(NA + 127) / 128, 256, SMEM_A_BYTES, aux.s2>>>(
        embA, embB, Waa, baa, Wba, bba, WnA, bnA,
        Waa1, baa1, Wab1, bab1, WnA1, bnA1, WnB1 + 4096, 1);
    k_gemmB<<<(NB + 127) / 128, 256, SMEM_B_BYTES, aux.s2>>>(
        embA, embB, Wab, bab, WnB, bnB,
        Wba1, bba1, WnB1, bnB1, WnA1 + 2 * 4096, 1);
    cudaEventRecord(aux.evJ, aux.s2);

    k_fill_all<<<(Etot + 255) / 256, 256>>>(src_aa, dst_aa, Eaa,
                                            src_ba, dst_ba, Eba,
                                            src_ab, dst_ab, Eab);

    // join, gather, then reset scratch for the next run (all on main stream)
    cudaStreamWaitEvent(0, aux.evJ, 0);
    k_gather<<<(NA + NB + 7) / 8, 256>>>(out);
    k_zero_end<<<(NTOT / 4 + 255) / 256, 256>>>();
}